// round 2
// baseline (speedup 1.0000x reference)
#include <cuda_runtime.h>
#include <math.h>

#define Bsz 512
#define Tt  256
#define Ii  256
#define Hh  512
#define Gg  2048   // 4H

// ---------------- scratch (device globals; no allocation allowed) ----------
__device__ float g_xg[(size_t)Bsz * Tt * Gg];   // 1.07 GB: x@Wih^T + bih + bhh
__device__ float g_hs[(size_t)Bsz * Tt * Hh];   // 256 MB: LSTM hidden outputs
__device__ float g_h [Bsz * Hh];
__device__ float g_c [Bsz * Hh];
__device__ float g_pre[Bsz * Gg];               // per-step gate preactivations

// ---------------- init ------------------------------------------------------
__global__ void init_state_kernel(float* __restrict__ h, float* __restrict__ c) {
    int i = blockIdx.x * blockDim.x + threadIdx.x;
    if (i < Bsz * Hh) { h[i] = 0.f; c[i] = 0.f; }
}

// ---------------- tiled NT SGEMM: C[m,n] = A[m,:]·Bw[n,:] + epilogue --------
// BM=128, BN=64, BK=16, 256 threads, each computes 8x4.
#define BM 128
#define BN 64
#define BK 16
#define TM 8
#define TN 4

// MODE 0: epilogue adds add0[n] + add1[n] (bias vectors)       (xg projection)
// MODE 1: epilogue adds add0[m*addStride + n]                  (recurrent step)
template <int MODE>
__global__ void __launch_bounds__(256) gemm_nt_kernel(
    const float* __restrict__ A,      // [M, K] row-major
    const float* __restrict__ Bw,     // [N, K] row-major
    const float* __restrict__ add0,
    const float* __restrict__ add1,
    float* __restrict__ C,            // [M, Gg] row-major (ldc = Gg)
    int K, int addStride)
{
    __shared__ float As[BK][BM];
    __shared__ float Bs[BK][BN];

    const int tid = threadIdx.x;
    const int m0 = blockIdx.y * BM;
    const int n0 = blockIdx.x * BN;

    const float* Aptr = A  + (size_t)m0 * K;
    const float* Bptr = Bw + (size_t)n0 * K;

    const int rowA = tid >> 2;            // 0..63
    const int colA = (tid & 3) * 4;       // 0,4,8,12
    const int rowB = tid >> 2;            // 0..63
    const int colB = (tid & 3) * 4;

    const int tr = tid >> 4;              // 0..15 (row group)
    const int tc = tid & 15;              // 0..15 (col group)

    float acc[TM][TN];
#pragma unroll
    for (int i = 0; i < TM; i++)
#pragma unroll
        for (int j = 0; j < TN; j++) acc[i][j] = 0.f;

    for (int kb = 0; kb < K; kb += BK) {
#pragma unroll
        for (int r = 0; r < 2; r++) {
            float4 v = *(const float4*)(Aptr + (size_t)(rowA + 64 * r) * K + kb + colA);
            As[colA + 0][rowA + 64 * r] = v.x;
            As[colA + 1][rowA + 64 * r] = v.y;
            As[colA + 2][rowA + 64 * r] = v.z;
            As[colA + 3][rowA + 64 * r] = v.w;
        }
        {
            float4 v = *(const float4*)(Bptr + (size_t)rowB * K + kb + colB);
            Bs[colB + 0][rowB] = v.x;
            Bs[colB + 1][rowB] = v.y;
            Bs[colB + 2][rowB] = v.z;
            Bs[colB + 3][rowB] = v.w;
        }
        __syncthreads();

#pragma unroll
        for (int k = 0; k < BK; k++) {
            float rm[TM], rn[TN];
#pragma unroll
            for (int i = 0; i < TM; i++) rm[i] = As[k][tr * TM + i];
#pragma unroll
            for (int j = 0; j < TN; j++) rn[j] = Bs[k][tc * TN + j];
#pragma unroll
            for (int i = 0; i < TM; i++)
#pragma unroll
                for (int j = 0; j < TN; j++) acc[i][j] += rm[i] * rn[j];
        }
        __syncthreads();
    }

#pragma unroll
    for (int i = 0; i < TM; i++) {
        const int m = m0 + tr * TM + i;
        const int n = n0 + tc * TN;
        float4 v;
        if (MODE == 0) {
            v.x = acc[i][0] + add0[n + 0] + add1[n + 0];
            v.y = acc[i][1] + add0[n + 1] + add1[n + 1];
            v.z = acc[i][2] + add0[n + 2] + add1[n + 2];
            v.w = acc[i][3] + add0[n + 3] + add1[n + 3];
        } else {
            const float* ap = add0 + (size_t)m * addStride + n;
            v.x = acc[i][0] + ap[0];
            v.y = acc[i][1] + ap[1];
            v.z = acc[i][2] + ap[2];
            v.w = acc[i][3] + ap[3];
        }
        *(float4*)(C + (size_t)m * Gg + n) = v;
    }
}

// ---------------- gates: i,f,g,o -> c,h ------------------------------------
__device__ __forceinline__ float sigmoidf_(float x) { return 1.f / (1.f + expf(-x)); }

__global__ void __launch_bounds__(512) gates_kernel(int t) {
    const int b = blockIdx.x;
    const int j = threadIdx.x;
    const float* pre = g_pre + (size_t)b * Gg;
    float ig = sigmoidf_(pre[j]);
    float fg = sigmoidf_(pre[j + Hh]);
    float gg = tanhf    (pre[j + 2 * Hh]);
    float og = sigmoidf_(pre[j + 3 * Hh]);
    const int idx = b * Hh + j;
    float c = fg * g_c[idx] + ig * gg;
    float h = og * tanhf(c);
    g_c[idx] = c;
    g_h[idx] = h;
    g_hs[((size_t)b * Tt + t) * Hh + j] = h;
}

// ---------------- fused head: fc1 + BN1 + leaky + fc2 + BN2 + relu ---------
// one block per t, 256 threads. dyn smem: fc1t[512*32] + sa[512*33]
#define HEAD_DYN_SMEM ((512 * 32 + 512 * 33) * sizeof(float))

__global__ void __launch_bounds__(256) head_kernel(
    const float* __restrict__ fc1_w, const float* __restrict__ fc1_b,
    const float* __restrict__ fc2_w, const float* __restrict__ fc2_b,
    const float* __restrict__ bn1_g, const float* __restrict__ bn1_b,
    const float* __restrict__ bn2_g, const float* __restrict__ bn2_b,
    float* __restrict__ out)
{
    extern __shared__ float sm[];
    float* fc1t = sm;              // [512][32]  k-major transposed fc1 weights
    float* sa   = sm + 512 * 32;   // [512][33]  a values, padded stride

    __shared__ float red1[8], red2[8];
    __shared__ float zbuf[Bsz];
    __shared__ float fc2s[32];
    __shared__ float stats[4];

    const int t = blockIdx.x;
    const int tid = threadIdx.x;
    const int warp = tid >> 5, lane = tid & 31;

    if (tid < 32) fc2s[tid] = fc2_w[tid];
    for (int idx = tid; idx < 32 * 512; idx += 256) {
        int o = idx >> 9, k = idx & 511;
        fc1t[k * 32 + o] = fc1_w[idx];
    }
    __syncthreads();

    // fc1: sa[b][o] = hs[b,t,:]·fc1_w[o,:] + fc1_b[o]; each warp handles 64 b's, 2 at a time
    const float bias_o = fc1_b[lane];
    for (int pr = 0; pr < 32; pr++) {
        const int b0 = warp * 64 + pr * 2;
        const int b1 = b0 + 1;
        const float4* r0 = (const float4*)(g_hs + ((size_t)b0 * Tt + t) * Hh);
        const float4* r1 = (const float4*)(g_hs + ((size_t)b1 * Tt + t) * Hh);
        float a0 = bias_o, a1 = bias_o;
#pragma unroll 4
        for (int k4 = 0; k4 < Hh / 4; k4++) {
            float4 v0 = r0[k4], v1 = r1[k4];
            const float* fp = fc1t + (k4 * 4) * 32 + lane;
            float w;
            w = fp[0];  a0 += v0.x * w; a1 += v1.x * w;
            w = fp[32]; a0 += v0.y * w; a1 += v1.y * w;
            w = fp[64]; a0 += v0.z * w; a1 += v1.z * w;
            w = fp[96]; a0 += v0.w * w; a1 += v1.w * w;
        }
        sa[b0 * 33 + lane] = a0;
        sa[b1 * 33 + lane] = a1;
    }
    __syncthreads();

    // BN1 stats over (B, 32) = 16384 values
    float s = 0.f, ss = 0.f;
    for (int idx = tid; idx < Bsz * 32; idx += 256) {
        float v = sa[(idx >> 5) * 33 + (idx & 31)];
        s += v; ss += v * v;
    }
#pragma unroll
    for (int off = 16; off; off >>= 1) {
        s  += __shfl_down_sync(0xffffffffu, s,  off);
        ss += __shfl_down_sync(0xffffffffu, ss, off);
    }
    if (lane == 0) { red1[warp] = s; red2[warp] = ss; }
    __syncthreads();
    if (tid == 0) {
        float S = 0.f, SS = 0.f;
        for (int w = 0; w < 8; w++) { S += red1[w]; SS += red2[w]; }
        float m = S / 16384.f;
        float v = SS / 16384.f - m * m;
        stats[0] = m;
        stats[1] = rsqrtf(v + 1e-5f);
    }
    __syncthreads();

    const float m1 = stats[0], inv1 = stats[1];
    const float g1 = bn1_g[t], be1 = bn1_b[t];
    const float f2b = fc2_b[0];

    // BN1 -> leaky -> fc2
    for (int b = tid; b < Bsz; b += 256) {
        float acc = f2b;
#pragma unroll
        for (int o = 0; o < 32; o++) {
            float a = (sa[b * 33 + o] - m1) * inv1 * g1 + be1;
            a = a > 0.f ? a : 0.1f * a;
            acc += a * fc2s[o];
        }
        zbuf[b] = acc;
    }
    __syncthreads();

    // BN2 stats over B
    float s2 = 0.f, ss2 = 0.f;
    for (int b = tid; b < Bsz; b += 256) { float v = zbuf[b]; s2 += v; ss2 += v * v; }
#pragma unroll
    for (int off = 16; off; off >>= 1) {
        s2  += __shfl_down_sync(0xffffffffu, s2,  off);
        ss2 += __shfl_down_sync(0xffffffffu, ss2, off);
    }
    if (lane == 0) { red1[warp] = s2; red2[warp] = ss2; }
    __syncthreads();
    if (tid == 0) {
        float S = 0.f, SS = 0.f;
        for (int w = 0; w < 8; w++) { S += red1[w]; SS += red2[w]; }
        float m = S / (float)Bsz;
        float v = SS / (float)Bsz - m * m;
        stats[2] = m;
        stats[3] = rsqrtf(v + 1e-5f);
    }
    __syncthreads();

    const float m2 = stats[2], inv2 = stats[3];
    const float g2 = bn2_g[t], be2 = bn2_b[t];
    for (int b = tid; b < Bsz; b += 256) {
        float v = (zbuf[b] - m2) * inv2 * g2 + be2;
        out[(size_t)b * Tt + t] = v > 0.f ? v : 0.f;
    }
}

// ---------------- launch ----------------------------------------------------
extern "C" void kernel_launch(void* const* d_in, const int* in_sizes, int n_in,
                              void* d_out, int out_size)
{
    const float* x     = (const float*)d_in[0];
    const float* Wih   = (const float*)d_in[1];
    const float* Whh   = (const float*)d_in[2];
    const float* bih   = (const float*)d_in[3];
    const float* bhh   = (const float*)d_in[4];
    const float* fc1_w = (const float*)d_in[5];
    const float* fc1_b = (const float*)d_in[6];
    const float* fc2_w = (const float*)d_in[7];
    const float* fc2_b = (const float*)d_in[8];
    const float* bn1_g = (const float*)d_in[9];
    const float* bn1_b = (const float*)d_in[10];
    const float* bn2_g = (const float*)d_in[11];
    const float* bn2_b = (const float*)d_in[12];
    float* out = (float*)d_out;

    cudaFuncSetAttribute(head_kernel, cudaFuncAttributeMaxDynamicSharedMemorySize,
                         (int)HEAD_DYN_SMEM);

    // Resolve DEVICE addresses of all scratch globals. (Passing a __device__
    // symbol directly from host code passes the host shadow address — that was
    // the round-1 bug: the scan GEMM read h from a bogus pointer.)
    float* d_xg  = nullptr;
    float* d_pre = nullptr;
    float* d_h   = nullptr;
    float* d_c   = nullptr;
    cudaGetSymbolAddress((void**)&d_xg,  g_xg);
    cudaGetSymbolAddress((void**)&d_pre, g_pre);
    cudaGetSymbolAddress((void**)&d_h,   g_h);
    cudaGetSymbolAddress((void**)&d_c,   g_c);

    // zero h, c
    init_state_kernel<<<(Bsz * Hh + 255) / 256, 256>>>(d_h, d_c);

    // xg = x @ Wih^T + bih + bhh   (M = B*T, N = 4H, K = I)
    {
        dim3 grid(Gg / BN, (Bsz * Tt) / BM);
        gemm_nt_kernel<0><<<grid, 256>>>(x, Wih, bih, bhh, d_xg, Ii, 0);
    }

    // recurrent scan
    for (int t = 0; t < Tt; t++) {
        dim3 grid(Gg / BN, Bsz / BM);   // 32 x 4 = 128 blocks
        gemm_nt_kernel<1><<<grid, 256>>>(d_h, Whh, d_xg + (size_t)t * Gg, nullptr,
                                         d_pre, Hh, Tt * Gg);
        gates_kernel<<<Bsz, Hh>>>(t);
    }

    // fused head
    head_kernel<<<Tt, 256, HEAD_DYN_SMEM>>>(fc1_w, fc1_b, fc2_w, fc2_b,
                                            bn1_g, bn1_b, bn2_g, bn2_b, out);
}

// round 3
// speedup vs baseline: 1.5132x; 1.5132x over previous
#include <cuda_runtime.h>
#include <cuda_bf16.h>
#include <math.h>
#include <stdint.h>

#define Bsz 512
#define Tt  256
#define Ii  256
#define Hh  512
#define Gg  2048   // 4H

// ---------------- scratch (device globals; no allocation allowed) ----------
__device__ __align__(256) float g_xg[(size_t)Bsz * Tt * Gg];   // 1.07 GB
__device__ __align__(256) float g_hs[(size_t)Bsz * Tt * Hh];   // 256 MB
__device__ __align__(256) float g_c [Bsz * Hh];
__device__ __align__(256) __nv_bfloat16 g_x_hi[(size_t)Bsz * Tt * Ii];
__device__ __align__(256) __nv_bfloat16 g_x_lo[(size_t)Bsz * Tt * Ii];
__device__ __align__(256) __nv_bfloat16 g_wih_hi[Ii * Gg];   // [256][2048] transposed
__device__ __align__(256) __nv_bfloat16 g_wih_lo[Ii * Gg];
__device__ __align__(256) __nv_bfloat16 g_whh_hi[Hh * Gg];   // [512][2048] transposed
__device__ __align__(256) __nv_bfloat16 g_whh_lo[Hh * Gg];
__device__ __align__(256) __nv_bfloat16 g_h_hi0[Bsz * Hh];
__device__ __align__(256) __nv_bfloat16 g_h_lo0[Bsz * Hh];
__device__ __align__(256) __nv_bfloat16 g_h_hi1[Bsz * Hh];
__device__ __align__(256) __nv_bfloat16 g_h_lo1[Bsz * Hh];

// ---------------- PTX helpers ----------------------------------------------
__device__ __forceinline__ uint32_t smem_u32(const void* p) {
    return (uint32_t)__cvta_generic_to_shared(p);
}
__device__ __forceinline__ void ldsm4(uint32_t* r, uint32_t addr) {
    asm volatile("ldmatrix.sync.aligned.m8n8.x4.shared.b16 {%0,%1,%2,%3},[%4];\n"
                 : "=r"(r[0]), "=r"(r[1]), "=r"(r[2]), "=r"(r[3]) : "r"(addr));
}
__device__ __forceinline__ void ldsm4t(uint32_t& r0, uint32_t& r1, uint32_t& r2, uint32_t& r3,
                                       uint32_t addr) {
    asm volatile("ldmatrix.sync.aligned.m8n8.x4.trans.shared.b16 {%0,%1,%2,%3},[%4];\n"
                 : "=r"(r0), "=r"(r1), "=r"(r2), "=r"(r3) : "r"(addr));
}
__device__ __forceinline__ void mma_bf16(float* c, const uint32_t* a, const uint32_t* b) {
    asm volatile("mma.sync.aligned.m16n8k16.row.col.f32.bf16.bf16.f32 "
                 "{%0,%1,%2,%3},{%4,%5,%6,%7},{%8,%9},{%0,%1,%2,%3};\n"
                 : "+f"(c[0]), "+f"(c[1]), "+f"(c[2]), "+f"(c[3])
                 : "r"(a[0]), "r"(a[1]), "r"(a[2]), "r"(a[3]), "r"(b[0]), "r"(b[1]));
}

// ---------------- prep kernels ---------------------------------------------
// src [N][K] fp32 -> transposed dst [K][N(=2048 stride)] bf16 hi/lo
__global__ void conv_w_kernel(const float* __restrict__ src,
                              __nv_bfloat16* __restrict__ dhi,
                              __nv_bfloat16* __restrict__ dlo, int N, int K) {
    int idx = blockIdx.x * 256 + threadIdx.x;
    if (idx >= N * K) return;
    int n = idx / K, k = idx - n * K;
    float v = src[idx];
    __nv_bfloat16 h = __float2bfloat16(v);
    dhi[(size_t)k * Gg + n] = h;
    dlo[(size_t)k * Gg + n] = __float2bfloat16(v - __bfloat162float(h));
}

__global__ void conv_x_kernel(const float* __restrict__ src,
                              __nv_bfloat16* __restrict__ dhi,
                              __nv_bfloat16* __restrict__ dlo, int n) {
    int idx = blockIdx.x * 256 + threadIdx.x;
    if (idx >= n) return;
    float v = src[idx];
    __nv_bfloat16 h = __float2bfloat16(v);
    dhi[idx] = h;
    dlo[idx] = __float2bfloat16(v - __bfloat162float(h));
}

__global__ void init_kernel(float* __restrict__ c,
                            __nv_bfloat16* __restrict__ hhi,
                            __nv_bfloat16* __restrict__ hlo) {
    int i = blockIdx.x * 256 + threadIdx.x;
    if (i < Bsz * Hh) {
        c[i] = 0.f;
        hhi[i] = __float2bfloat16(0.f);
        hlo[i] = __float2bfloat16(0.f);
    }
}

// ---------------- xg GEMM: C = x @ Wih^T + bih + bhh (bf16x2 MMA) ----------
// CTA tile 128(M) x 128(N), BK=32. 8 warps as 4(m) x 2(n). Warp: 32x64.
__global__ void __launch_bounds__(256) xg_gemm_kernel(
    const __nv_bfloat16* __restrict__ Ahi, const __nv_bfloat16* __restrict__ Alo,
    const __nv_bfloat16* __restrict__ Bhi, const __nv_bfloat16* __restrict__ Blo,
    const float* __restrict__ bih, const float* __restrict__ bhh,
    float* __restrict__ C)
{
    __shared__ __align__(16) __nv_bfloat16 sA[2][128][40];
    __shared__ __align__(16) __nv_bfloat16 sB[2][32][136];
    const int tid = threadIdx.x;
    const int l = tid & 31, w = tid >> 5;
    const int wm = w >> 1, wn = w & 1;
    const int n0 = blockIdx.x * 128;
    const int m0 = blockIdx.y * 128;

    float acc[2][8][4];
#pragma unroll
    for (int mi = 0; mi < 2; mi++)
#pragma unroll
        for (int nt = 0; nt < 8; nt++)
#pragma unroll
            for (int q = 0; q < 4; q++) acc[mi][nt][q] = 0.f;

    for (int k0 = 0; k0 < Ii; k0 += 32) {
        for (int s = tid; s < 512; s += 256) {
            int row = s >> 2, ch = (s & 3) * 8;
            *(uint4*)&sA[0][row][ch] = *(const uint4*)(Ahi + (size_t)(m0 + row) * Ii + k0 + ch);
            *(uint4*)&sA[1][row][ch] = *(const uint4*)(Alo + (size_t)(m0 + row) * Ii + k0 + ch);
        }
        for (int s = tid; s < 512; s += 256) {
            int kr = s >> 4, ch = (s & 15) * 8;
            *(uint4*)&sB[0][kr][ch] = *(const uint4*)(Bhi + (size_t)(k0 + kr) * Gg + n0 + ch);
            *(uint4*)&sB[1][kr][ch] = *(const uint4*)(Blo + (size_t)(k0 + kr) * Gg + n0 + ch);
        }
        __syncthreads();
#pragma unroll
        for (int kk = 0; kk < 32; kk += 16) {
            uint32_t af[2][2][4];
#pragma unroll
            for (int p = 0; p < 2; p++)
#pragma unroll
                for (int mi = 0; mi < 2; mi++) {
                    uint32_t addr = smem_u32(
                        &sA[p][wm * 32 + mi * 16 + (l & 7) + ((l >> 3) & 1) * 8][kk + (l >> 4) * 8]);
                    ldsm4(af[p][mi], addr);
                }
            uint32_t bfr[2][8][2];
            const int lm = l & 15;
            const int krow = (lm & 7) + ((lm >> 3) & 1) * 8;
            const int csel = (l >> 4) * 8;
#pragma unroll
            for (int p = 0; p < 2; p++)
#pragma unroll
                for (int jp = 0; jp < 4; jp++) {
                    uint32_t addr = smem_u32(&sB[p][kk + krow][wn * 64 + jp * 16 + csel]);
                    uint32_t r0, r1, r2, r3;
                    ldsm4t(r0, r1, r2, r3, addr);
                    bfr[p][jp * 2][0] = r0; bfr[p][jp * 2][1] = r1;
                    bfr[p][jp * 2 + 1][0] = r2; bfr[p][jp * 2 + 1][1] = r3;
                }
#pragma unroll
            for (int mi = 0; mi < 2; mi++)
#pragma unroll
                for (int nt = 0; nt < 8; nt++) {
                    mma_bf16(acc[mi][nt], af[0][mi], bfr[0][nt]);
                    mma_bf16(acc[mi][nt], af[0][mi], bfr[1][nt]);
                    mma_bf16(acc[mi][nt], af[1][mi], bfr[0][nt]);
                }
        }
        __syncthreads();
    }

    const int r = l >> 2, cq = (l & 3) * 2;
#pragma unroll
    for (int mi = 0; mi < 2; mi++)
#pragma unroll
        for (int nt = 0; nt < 8; nt++) {
            const int col = n0 + wn * 64 + nt * 8 + cq;
            float bs0 = bih[col] + bhh[col];
            float bs1 = bih[col + 1] + bhh[col + 1];
#pragma unroll
            for (int rr = 0; rr < 2; rr++) {
                int m = m0 + wm * 32 + mi * 16 + r + rr * 8;
                float2 v = make_float2(acc[mi][nt][rr * 2 + 0] + bs0,
                                       acc[mi][nt][rr * 2 + 1] + bs1);
                *(float2*)(C + (size_t)m * Gg + col) = v;
            }
        }
}

// ---------------- fused scan step: pre = h@Whh^T + xg, gates, c/h update ---
// CTA tile: 64 batches x (32 h-cols across 4 gates). BK=32. 8 warps 2(m) x 4(n).
// Warp: 32 batches x (8 cols x 4 gates). Grid (Hh/32, Bsz/64) = (16, 8).
__global__ void __launch_bounds__(256) scan_step_kernel(
    const __nv_bfloat16* __restrict__ Bhi, const __nv_bfloat16* __restrict__ Blo,
    const __nv_bfloat16* __restrict__ hr_hi, const __nv_bfloat16* __restrict__ hr_lo,
    __nv_bfloat16* __restrict__ hw_hi, __nv_bfloat16* __restrict__ hw_lo,
    const float* __restrict__ xg_t, float* __restrict__ c_st,
    float* __restrict__ hs_t)
{
    __shared__ __align__(16) __nv_bfloat16 sA[2][64][40];
    __shared__ __align__(16) __nv_bfloat16 sB[2][32][136];
    const int tid = threadIdx.x;
    const int l = tid & 31, w = tid >> 5;
    const int wm = w >> 2, wn = w & 3;
    const int ct = blockIdx.x;
    const int mb = blockIdx.y * 64;

    float acc[2][4][4];
#pragma unroll
    for (int mi = 0; mi < 2; mi++)
#pragma unroll
        for (int g = 0; g < 4; g++)
#pragma unroll
            for (int q = 0; q < 4; q++) acc[mi][g][q] = 0.f;

    const int arow = tid >> 2, ach = (tid & 3) * 8;

    for (int k0 = 0; k0 < Hh; k0 += 32) {
        *(uint4*)&sA[0][arow][ach] = *(const uint4*)(hr_hi + (size_t)(mb + arow) * Hh + k0 + ach);
        *(uint4*)&sA[1][arow][ach] = *(const uint4*)(hr_lo + (size_t)(mb + arow) * Hh + k0 + ach);
        for (int s = tid; s < 512; s += 256) {
            int kr = s >> 4, ch = s & 15;
            int gate = ch >> 2, cl = (ch & 3) * 8;
            *(uint4*)&sB[0][kr][gate * 32 + cl] =
                *(const uint4*)(Bhi + (size_t)(k0 + kr) * Gg + gate * Hh + ct * 32 + cl);
            *(uint4*)&sB[1][kr][gate * 32 + cl] =
                *(const uint4*)(Blo + (size_t)(k0 + kr) * Gg + gate * Hh + ct * 32 + cl);
        }
        __syncthreads();
#pragma unroll
        for (int kk = 0; kk < 32; kk += 16) {
            uint32_t af[2][2][4];
#pragma unroll
            for (int p = 0; p < 2; p++)
#pragma unroll
                for (int mi = 0; mi < 2; mi++) {
                    uint32_t addr = smem_u32(
                        &sA[p][wm * 32 + mi * 16 + (l & 7) + ((l >> 3) & 1) * 8][kk + (l >> 4) * 8]);
                    ldsm4(af[p][mi], addr);
                }
            uint32_t bfr[2][4][2];
            const int lm = l & 15;
            const int krow = (lm & 7) + ((lm >> 3) & 1) * 8;
            const int gsel = l >> 4;
#pragma unroll
            for (int p = 0; p < 2; p++)
#pragma unroll
                for (int gp = 0; gp < 2; gp++) {
                    uint32_t addr = smem_u32(&sB[p][kk + krow][(gp * 2 + gsel) * 32 + wn * 8]);
                    uint32_t r0, r1, r2, r3;
                    ldsm4t(r0, r1, r2, r3, addr);
                    bfr[p][gp * 2][0] = r0; bfr[p][gp * 2][1] = r1;
                    bfr[p][gp * 2 + 1][0] = r2; bfr[p][gp * 2 + 1][1] = r3;
                }
#pragma unroll
            for (int mi = 0; mi < 2; mi++)
#pragma unroll
                for (int g = 0; g < 4; g++) {
                    mma_bf16(acc[mi][g], af[0][mi], bfr[0][g]);
                    mma_bf16(acc[mi][g], af[0][mi], bfr[1][g]);
                    mma_bf16(acc[mi][g], af[1][mi], bfr[0][g]);
                }
        }
        __syncthreads();
    }

    // fused gate epilogue
    const int r = l >> 2, cq = (l & 3) * 2;
    const int col = ct * 32 + wn * 8 + cq;
#pragma unroll
    for (int mi = 0; mi < 2; mi++) {
#pragma unroll
        for (int rr = 0; rr < 2; rr++) {
            int b = mb + wm * 32 + mi * 16 + r + rr * 8;
            const float* xp = xg_t + (size_t)b * ((size_t)Tt * Gg);
            float2 cold = *(const float2*)(c_st + (size_t)b * Hh + col);
            float cn[2], hn[2];
#pragma unroll
            for (int cc = 0; cc < 2; cc++) {
                float pi = acc[mi][0][rr * 2 + cc] + xp[0 * Hh + col + cc];
                float pf = acc[mi][1][rr * 2 + cc] + xp[1 * Hh + col + cc];
                float pg = acc[mi][2][rr * 2 + cc] + xp[2 * Hh + col + cc];
                float po = acc[mi][3][rr * 2 + cc] + xp[3 * Hh + col + cc];
                float ig = 1.f / (1.f + expf(-pi));
                float fg = 1.f / (1.f + expf(-pf));
                float gg = tanhf(pg);
                float og = 1.f / (1.f + expf(-po));
                float cv = fg * (cc ? cold.y : cold.x) + ig * gg;
                cn[cc] = cv;
                hn[cc] = og * tanhf(cv);
            }
            *(float2*)(c_st + (size_t)b * Hh + col) = make_float2(cn[0], cn[1]);
            *(float2*)(hs_t + (size_t)b * ((size_t)Tt * Hh) + col) = make_float2(hn[0], hn[1]);
            __nv_bfloat16 h0 = __float2bfloat16(hn[0]);
            __nv_bfloat16 h1 = __float2bfloat16(hn[1]);
            __nv_bfloat162 hh; hh.x = h0; hh.y = h1;
            *(__nv_bfloat162*)(hw_hi + (size_t)b * Hh + col) = hh;
            __nv_bfloat162 ll;
            ll.x = __float2bfloat16(hn[0] - __bfloat162float(h0));
            ll.y = __float2bfloat16(hn[1] - __bfloat162float(h1));
            *(__nv_bfloat162*)(hw_lo + (size_t)b * Hh + col) = ll;
        }
    }
}

// ---------------- fused head: fc1 + BN1 + leaky + fc2 + BN2 + relu ---------
#define HEAD_DYN_SMEM ((512 * 32 + 512 * 33) * sizeof(float))

__global__ void __launch_bounds__(256) head_kernel(
    const float* __restrict__ fc1_w, const float* __restrict__ fc1_b,
    const float* __restrict__ fc2_w, const float* __restrict__ fc2_b,
    const float* __restrict__ bn1_g, const float* __restrict__ bn1_b,
    const float* __restrict__ bn2_g, const float* __restrict__ bn2_b,
    float* __restrict__ out)
{
    extern __shared__ float sm[];
    float* fc1t = sm;              // [512][32]
    float* sa   = sm + 512 * 32;   // [512][33]

    __shared__ float red1[8], red2[8];
    __shared__ float zbuf[Bsz];
    __shared__ float fc2s[32];
    __shared__ float stats[4];

    const int t = blockIdx.x;
    const int tid = threadIdx.x;
    const int warp = tid >> 5, lane = tid & 31;

    if (tid < 32) fc2s[tid] = fc2_w[tid];
    for (int idx = tid; idx < 32 * 512; idx += 256) {
        int o = idx >> 9, k = idx & 511;
        fc1t[k * 32 + o] = fc1_w[idx];
    }
    __syncthreads();

    const float bias_o = fc1_b[lane];
    for (int pr = 0; pr < 32; pr++) {
        const int b0 = warp * 64 + pr * 2;
        const int b1 = b0 + 1;
        const float4* r0 = (const float4*)(g_hs + ((size_t)b0 * Tt + t) * Hh);
        const float4* r1 = (const float4*)(g_hs + ((size_t)b1 * Tt + t) * Hh);
        float a0 = bias_o, a1 = bias_o;
#pragma unroll 4
        for (int k4 = 0; k4 < Hh / 4; k4++) {
            float4 v0 = r0[k4], v1 = r1[k4];
            const float* fp = fc1t + (k4 * 4) * 32 + lane;
            float wv;
            wv = fp[0];  a0 += v0.x * wv; a1 += v1.x * wv;
            wv = fp[32]; a0 += v0.y * wv; a1 += v1.y * wv;
            wv = fp[64]; a0 += v0.z * wv; a1 += v1.z * wv;
            wv = fp[96]; a0 += v0.w * wv; a1 += v1.w * wv;
        }
        sa[b0 * 33 + lane] = a0;
        sa[b1 * 33 + lane] = a1;
    }
    __syncthreads();

    float s = 0.f, ss = 0.f;
    for (int idx = tid; idx < Bsz * 32; idx += 256) {
        float v = sa[(idx >> 5) * 33 + (idx & 31)];
        s += v; ss += v * v;
    }
#pragma unroll
    for (int off = 16; off; off >>= 1) {
        s  += __shfl_down_sync(0xffffffffu, s,  off);
        ss += __shfl_down_sync(0xffffffffu, ss, off);
    }
    if (lane == 0) { red1[warp] = s; red2[warp] = ss; }
    __syncthreads();
    if (tid == 0) {
        float S = 0.f, SS = 0.f;
        for (int wv = 0; wv < 8; wv++) { S += red1[wv]; SS += red2[wv]; }
        float m = S / 16384.f;
        float v = SS / 16384.f - m * m;
        stats[0] = m;
        stats[1] = rsqrtf(v + 1e-5f);
    }
    __syncthreads();

    const float m1 = stats[0], inv1 = stats[1];
    const float g1 = bn1_g[t], be1 = bn1_b[t];
    const float f2b = fc2_b[0];

    for (int b = tid; b < Bsz; b += 256) {
        float acc = f2b;
#pragma unroll
        for (int o = 0; o < 32; o++) {
            float a = (sa[b * 33 + o] - m1) * inv1 * g1 + be1;
            a = a > 0.f ? a : 0.1f * a;
            acc += a * fc2s[o];
        }
        zbuf[b] = acc;
    }
    __syncthreads();

    float s2 = 0.f, ss2 = 0.f;
    for (int b = tid; b < Bsz; b += 256) { float v = zbuf[b]; s2 += v; ss2 += v * v; }
#pragma unroll
    for (int off = 16; off; off >>= 1) {
        s2  += __shfl_down_sync(0xffffffffu, s2,  off);
        ss2 += __shfl_down_sync(0xffffffffu, ss2, off);
    }
    if (lane == 0) { red1[warp] = s2; red2[warp] = ss2; }
    __syncthreads();
    if (tid == 0) {
        float S = 0.f, SS = 0.f;
        for (int wv = 0; wv < 8; wv++) { S += red1[wv]; SS += red2[wv]; }
        float m = S / (float)Bsz;
        float v = SS / (float)Bsz - m * m;
        stats[2] = m;
        stats[3] = rsqrtf(v + 1e-5f);
    }
    __syncthreads();

    const float m2 = stats[2], inv2 = stats[3];
    const float g2 = bn2_g[t], be2 = bn2_b[t];
    for (int b = tid; b < Bsz; b += 256) {
        float v = (zbuf[b] - m2) * inv2 * g2 + be2;
        out[(size_t)b * Tt + t] = v > 0.f ? v : 0.f;
    }
}

// ---------------- launch ----------------------------------------------------
extern "C" void kernel_launch(void* const* d_in, const int* in_sizes, int n_in,
                              void* d_out, int out_size)
{
    const float* x     = (const float*)d_in[0];
    const float* Wih   = (const float*)d_in[1];
    const float* Whh   = (const float*)d_in[2];
    const float* bih   = (const float*)d_in[3];
    const float* bhh   = (const float*)d_in[4];
    const float* fc1_w = (const float*)d_in[5];
    const float* fc1_b = (const float*)d_in[6];
    const float* fc2_w = (const float*)d_in[7];
    const float* fc2_b = (const float*)d_in[8];
    const float* bn1_g = (const float*)d_in[9];
    const float* bn1_b = (const float*)d_in[10];
    const float* bn2_g = (const float*)d_in[11];
    const float* bn2_b = (const float*)d_in[12];
    float* out = (float*)d_out;

    cudaFuncSetAttribute(head_kernel, cudaFuncAttributeMaxDynamicSharedMemorySize,
                         (int)HEAD_DYN_SMEM);

    float *d_xg, *d_hs, *d_c;
    __nv_bfloat16 *d_xhi, *d_xlo, *d_wihhi, *d_wihlo, *d_whhhi, *d_whhlo;
    __nv_bfloat16 *d_hhi0, *d_hlo0, *d_hhi1, *d_hlo1;
    cudaGetSymbolAddress((void**)&d_xg,    g_xg);
    cudaGetSymbolAddress((void**)&d_hs,    g_hs);
    cudaGetSymbolAddress((void**)&d_c,     g_c);
    cudaGetSymbolAddress((void**)&d_xhi,   g_x_hi);
    cudaGetSymbolAddress((void**)&d_xlo,   g_x_lo);
    cudaGetSymbolAddress((void**)&d_wihhi, g_wih_hi);
    cudaGetSymbolAddress((void**)&d_wihlo, g_wih_lo);
    cudaGetSymbolAddress((void**)&d_whhhi, g_whh_hi);
    cudaGetSymbolAddress((void**)&d_whhlo, g_whh_lo);
    cudaGetSymbolAddress((void**)&d_hhi0,  g_h_hi0);
    cudaGetSymbolAddress((void**)&d_hlo0,  g_h_lo0);
    cudaGetSymbolAddress((void**)&d_hhi1,  g_h_hi1);
    cudaGetSymbolAddress((void**)&d_hlo1,  g_h_lo1);

    // prep: weight transposes + hi/lo splits, x split, state init
    conv_w_kernel<<<(Gg * Hh + 255) / 256, 256>>>(Whh, d_whhhi, d_whhlo, Gg, Hh);
    conv_w_kernel<<<(Gg * Ii + 255) / 256, 256>>>(Wih, d_wihhi, d_wihlo, Gg, Ii);
    conv_x_kernel<<<((int)((size_t)Bsz * Tt * Ii) + 255) / 256, 256>>>(
        x, d_xhi, d_xlo, Bsz * Tt * Ii);
    init_kernel<<<(Bsz * Hh + 255) / 256, 256>>>(d_c, d_hhi0, d_hlo0);

    // xg = x @ Wih^T + bih + bhh
    xg_gemm_kernel<<<dim3(Gg / 128, (Bsz * Tt) / 128), 256>>>(
        d_xhi, d_xlo, d_wihhi, d_wihlo, bih, bhh, d_xg);

    // recurrent scan (fused GEMM + gates), h double-buffered
    for (int t = 0; t < Tt; t++) {
        const __nv_bfloat16* rhi = (t & 1) ? d_hhi1 : d_hhi0;
        const __nv_bfloat16* rlo = (t & 1) ? d_hlo1 : d_hlo0;
        __nv_bfloat16* whi = (t & 1) ? d_hhi0 : d_hhi1;
        __nv_bfloat16* wlo = (t & 1) ? d_hlo0 : d_hlo1;
        scan_step_kernel<<<dim3(Hh / 32, Bsz / 64), 256>>>(
            d_whhhi, d_whhlo, rhi, rlo, whi, wlo,
            d_xg + (size_t)t * Gg, d_c, d_hs + (size_t)t * Hh);
    }

    // fused head
    head_kernel<<<Tt, 256, HEAD_DYN_SMEM>>>(fc1_w, fc1_b, fc2_w, fc2_b,
                                            bn1_g, bn1_b, bn2_g, bn2_b, out);
}

// round 4
// speedup vs baseline: 2.0531x; 1.3568x over previous
#include <cuda_runtime.h>
#include <cuda_bf16.h>
#include <math.h>
#include <stdint.h>

#define Bsz 512
#define Tt  256
#define Ii  256
#define Hh  512
#define Gg  2048   // 4H
#define NCTA 128   // persistent scan grid

// ---------------- scratch (device globals; no allocation allowed) ----------
__device__ __align__(256) float g_xg[(size_t)Bsz * Tt * Gg];   // 1.07 GB
__device__ __align__(256) float g_hs[(size_t)Bsz * Tt * Hh];   // 256 MB
__device__ __align__(256) __nv_bfloat16 g_x_hi[(size_t)Bsz * Tt * Ii];
__device__ __align__(256) __nv_bfloat16 g_x_lo[(size_t)Bsz * Tt * Ii];
__device__ __align__(256) __nv_bfloat16 g_wih_hi[Ii * Gg];   // [256][2048] transposed
__device__ __align__(256) __nv_bfloat16 g_wih_lo[Ii * Gg];
__device__ __align__(256) __nv_bfloat16 g_whh_hi[Hh * Gg];   // [512][2048] transposed
__device__ __align__(256) __nv_bfloat16 g_whh_lo[Hh * Gg];
__device__ __align__(256) __nv_bfloat16 g_h_hi0[Bsz * Hh];
__device__ __align__(256) __nv_bfloat16 g_h_lo0[Bsz * Hh];
__device__ __align__(256) __nv_bfloat16 g_h_hi1[Bsz * Hh];
__device__ __align__(256) __nv_bfloat16 g_h_lo1[Bsz * Hh];
__device__ unsigned g_bar;   // software grid barrier counter (zeroed per launch)

// ---------------- PTX helpers ----------------------------------------------
__device__ __forceinline__ uint32_t smem_u32(const void* p) {
    return (uint32_t)__cvta_generic_to_shared(p);
}
__device__ __forceinline__ void ldsm4(uint32_t* r, uint32_t addr) {
    asm volatile("ldmatrix.sync.aligned.m8n8.x4.shared.b16 {%0,%1,%2,%3},[%4];\n"
                 : "=r"(r[0]), "=r"(r[1]), "=r"(r[2]), "=r"(r[3]) : "r"(addr));
}
__device__ __forceinline__ void ldsm4t(uint32_t& r0, uint32_t& r1, uint32_t& r2, uint32_t& r3,
                                       uint32_t addr) {
    asm volatile("ldmatrix.sync.aligned.m8n8.x4.trans.shared.b16 {%0,%1,%2,%3},[%4];\n"
                 : "=r"(r0), "=r"(r1), "=r"(r2), "=r"(r3) : "r"(addr));
}
__device__ __forceinline__ void mma_bf16(float* c, const uint32_t* a, const uint32_t* b) {
    asm volatile("mma.sync.aligned.m16n8k16.row.col.f32.bf16.bf16.f32 "
                 "{%0,%1,%2,%3},{%4,%5,%6,%7},{%8,%9},{%0,%1,%2,%3};\n"
                 : "+f"(c[0]), "+f"(c[1]), "+f"(c[2]), "+f"(c[3])
                 : "r"(a[0]), "r"(a[1]), "r"(a[2]), "r"(a[3]), "r"(b[0]), "r"(b[1]));
}
// L2-only vector load (bypass L1 — h crosses the software barrier between SMs)
__device__ __forceinline__ uint4 ldcg4(const void* p) {
    uint4 v;
    asm volatile("ld.global.cg.v4.u32 {%0,%1,%2,%3},[%4];\n"
                 : "=r"(v.x), "=r"(v.y), "=r"(v.z), "=r"(v.w) : "l"(p));
    return v;
}

__device__ __forceinline__ float fast_sigmoid(float x) {
    return __fdividef(1.f, 1.f + __expf(-x));
}
__device__ __forceinline__ float fast_tanh(float x) {
    return 1.f - __fdividef(2.f, __expf(2.f * x) + 1.f);
}

// ---------------- prep kernels ---------------------------------------------
__global__ void conv_w_kernel(const float* __restrict__ src,
                              __nv_bfloat16* __restrict__ dhi,
                              __nv_bfloat16* __restrict__ dlo, int N, int K) {
    int idx = blockIdx.x * 256 + threadIdx.x;
    if (idx >= N * K) return;
    int n = idx / K, k = idx - n * K;
    float v = src[idx];
    __nv_bfloat16 h = __float2bfloat16(v);
    dhi[(size_t)k * Gg + n] = h;
    dlo[(size_t)k * Gg + n] = __float2bfloat16(v - __bfloat162float(h));
}

__global__ void conv_x_kernel(const float* __restrict__ src,
                              __nv_bfloat16* __restrict__ dhi,
                              __nv_bfloat16* __restrict__ dlo, int n) {
    int idx = blockIdx.x * 256 + threadIdx.x;
    if (idx >= n) return;
    float v = src[idx];
    __nv_bfloat16 h = __float2bfloat16(v);
    dhi[idx] = h;
    dlo[idx] = __float2bfloat16(v - __bfloat162float(h));
}

__global__ void init_kernel(__nv_bfloat16* __restrict__ hhi,
                            __nv_bfloat16* __restrict__ hlo) {
    int i = blockIdx.x * 256 + threadIdx.x;
    if (i == 0) g_bar = 0u;
    if (i < Bsz * Hh) {
        hhi[i] = __float2bfloat16(0.f);
        hlo[i] = __float2bfloat16(0.f);
    }
}

// ---------------- xg GEMM: C = x @ Wih^T + bih + bhh (bf16x3 MMA) ----------
__global__ void __launch_bounds__(256) xg_gemm_kernel(
    const __nv_bfloat16* __restrict__ Ahi, const __nv_bfloat16* __restrict__ Alo,
    const __nv_bfloat16* __restrict__ Bhi, const __nv_bfloat16* __restrict__ Blo,
    const float* __restrict__ bih, const float* __restrict__ bhh,
    float* __restrict__ C)
{
    __shared__ __align__(16) __nv_bfloat16 sA[2][128][40];
    __shared__ __align__(16) __nv_bfloat16 sB[2][32][136];
    const int tid = threadIdx.x;
    const int l = tid & 31, w = tid >> 5;
    const int wm = w >> 1, wn = w & 1;
    const int n0 = blockIdx.x * 128;
    const int m0 = blockIdx.y * 128;

    float acc[2][8][4];
#pragma unroll
    for (int mi = 0; mi < 2; mi++)
#pragma unroll
        for (int nt = 0; nt < 8; nt++)
#pragma unroll
            for (int q = 0; q < 4; q++) acc[mi][nt][q] = 0.f;

    for (int k0 = 0; k0 < Ii; k0 += 32) {
        for (int s = tid; s < 512; s += 256) {
            int row = s >> 2, ch = (s & 3) * 8;
            *(uint4*)&sA[0][row][ch] = *(const uint4*)(Ahi + (size_t)(m0 + row) * Ii + k0 + ch);
            *(uint4*)&sA[1][row][ch] = *(const uint4*)(Alo + (size_t)(m0 + row) * Ii + k0 + ch);
        }
        for (int s = tid; s < 512; s += 256) {
            int kr = s >> 4, ch = (s & 15) * 8;
            *(uint4*)&sB[0][kr][ch] = *(const uint4*)(Bhi + (size_t)(k0 + kr) * Gg + n0 + ch);
            *(uint4*)&sB[1][kr][ch] = *(const uint4*)(Blo + (size_t)(k0 + kr) * Gg + n0 + ch);
        }
        __syncthreads();
#pragma unroll
        for (int kk = 0; kk < 32; kk += 16) {
            uint32_t af[2][2][4];
#pragma unroll
            for (int p = 0; p < 2; p++)
#pragma unroll
                for (int mi = 0; mi < 2; mi++) {
                    uint32_t addr = smem_u32(
                        &sA[p][wm * 32 + mi * 16 + (l & 7) + ((l >> 3) & 1) * 8][kk + (l >> 4) * 8]);
                    ldsm4(af[p][mi], addr);
                }
            uint32_t bfr[2][8][2];
            const int lm = l & 15;
            const int krow = (lm & 7) + ((lm >> 3) & 1) * 8;
            const int csel = (l >> 4) * 8;
#pragma unroll
            for (int p = 0; p < 2; p++)
#pragma unroll
                for (int jp = 0; jp < 4; jp++) {
                    uint32_t addr = smem_u32(&sB[p][kk + krow][wn * 64 + jp * 16 + csel]);
                    uint32_t r0, r1, r2, r3;
                    ldsm4t(r0, r1, r2, r3, addr);
                    bfr[p][jp * 2][0] = r0; bfr[p][jp * 2][1] = r1;
                    bfr[p][jp * 2 + 1][0] = r2; bfr[p][jp * 2 + 1][1] = r3;
                }
#pragma unroll
            for (int mi = 0; mi < 2; mi++)
#pragma unroll
                for (int nt = 0; nt < 8; nt++) {
                    mma_bf16(acc[mi][nt], af[0][mi], bfr[0][nt]);
                    mma_bf16(acc[mi][nt], af[0][mi], bfr[1][nt]);
                    mma_bf16(acc[mi][nt], af[1][mi], bfr[0][nt]);
                }
        }
        __syncthreads();
    }

    const int r = l >> 2, cq = (l & 3) * 2;
#pragma unroll
    for (int mi = 0; mi < 2; mi++)
#pragma unroll
        for (int nt = 0; nt < 8; nt++) {
            const int col = n0 + wn * 64 + nt * 8 + cq;
            float bs0 = bih[col] + bhh[col];
            float bs1 = bih[col + 1] + bhh[col + 1];
#pragma unroll
            for (int rr = 0; rr < 2; rr++) {
                int m = m0 + wm * 32 + mi * 16 + r + rr * 8;
                float2 v = make_float2(acc[mi][nt][rr * 2 + 0] + bs0,
                                       acc[mi][nt][rr * 2 + 1] + bs1);
                *(float2*)(C + (size_t)m * Gg + col) = v;
            }
        }
}

// ---------------- persistent scan: all 256 timesteps in ONE kernel ----------
// 128 CTAs (all co-resident), tile 64 b x (32 hcol x 4 gates). c lives in regs.
__global__ void __launch_bounds__(256) scan_persist_kernel(
    const __nv_bfloat16* __restrict__ Bhi, const __nv_bfloat16* __restrict__ Blo,
    __nv_bfloat16* __restrict__ h_hi0, __nv_bfloat16* __restrict__ h_lo0,
    __nv_bfloat16* __restrict__ h_hi1, __nv_bfloat16* __restrict__ h_lo1,
    const float* __restrict__ xg, float* __restrict__ hs)
{
    __shared__ __align__(16) __nv_bfloat16 sA[2][64][40];
    __shared__ __align__(16) __nv_bfloat16 sB[2][32][136];
    const int tid = threadIdx.x;
    const int l = tid & 31, w = tid >> 5;
    const int wm = w >> 2, wn = w & 3;
    const int bid = blockIdx.x;
    const int ct = bid & 15;            // hcol tile (16)
    const int mb = (bid >> 4) * 64;     // batch tile (8)

    const int r = l >> 2, cq = (l & 3) * 2;
    const int col = ct * 32 + wn * 8 + cq;

    // A staging indices
    const int arow = tid >> 2, ach = (tid & 3) * 8;
    // B staging indices (two slots per thread)
    const int kr0 = tid >> 4,         ch0 = tid & 15;
    const int g0 = ch0 >> 2,          cl0 = (ch0 & 3) * 8;
    const int kr1 = (tid + 256) >> 4, ch1 = (tid + 256) & 15;
    const int g1 = ch1 >> 2,          cl1 = (ch1 & 3) * 8;

    float c_reg[2][2][2];
#pragma unroll
    for (int mi = 0; mi < 2; mi++)
#pragma unroll
        for (int rr = 0; rr < 2; rr++)
#pragma unroll
            for (int cc = 0; cc < 2; cc++) c_reg[mi][rr][cc] = 0.f;

    for (int t = 0; t < Tt; t++) {
        const __nv_bfloat16* rhi = (t & 1) ? h_hi1 : h_hi0;
        const __nv_bfloat16* rlo = (t & 1) ? h_lo1 : h_lo0;
        __nv_bfloat16* whi = (t & 1) ? h_hi0 : h_hi1;
        __nv_bfloat16* wlo = (t & 1) ? h_lo0 : h_lo1;

        // prefetch xg epilogue operands (DRAM latency hides under the K loop)
        float2 xv[2][2][4];
#pragma unroll
        for (int mi = 0; mi < 2; mi++)
#pragma unroll
            for (int rr = 0; rr < 2; rr++) {
                int b = mb + wm * 32 + mi * 16 + r + rr * 8;
                const float* base = xg + ((size_t)b * Tt + t) * Gg;
#pragma unroll
                for (int g = 0; g < 4; g++)
                    xv[mi][rr][g] = *(const float2*)(base + g * Hh + col);
            }

        float acc[2][4][4];
#pragma unroll
        for (int mi = 0; mi < 2; mi++)
#pragma unroll
            for (int g = 0; g < 4; g++)
#pragma unroll
                for (int q = 0; q < 4; q++) acc[mi][g][q] = 0.f;

        // ---- K loop with register double-buffering ----
        uint4 rA[2], rB[2][2];
        {   // prologue: chunk 0
            const int k0 = 0;
            rA[0] = ldcg4(rhi + (size_t)(mb + arow) * Hh + k0 + ach);
            rA[1] = ldcg4(rlo + (size_t)(mb + arow) * Hh + k0 + ach);
            rB[0][0] = *(const uint4*)(Bhi + (size_t)(k0 + kr0) * Gg + g0 * Hh + ct * 32 + cl0);
            rB[1][0] = *(const uint4*)(Blo + (size_t)(k0 + kr0) * Gg + g0 * Hh + ct * 32 + cl0);
            rB[0][1] = *(const uint4*)(Bhi + (size_t)(k0 + kr1) * Gg + g1 * Hh + ct * 32 + cl1);
            rB[1][1] = *(const uint4*)(Blo + (size_t)(k0 + kr1) * Gg + g1 * Hh + ct * 32 + cl1);
        }

        for (int kc = 0; kc < 16; kc++) {
            // stage current chunk to smem
            *(uint4*)&sA[0][arow][ach] = rA[0];
            *(uint4*)&sA[1][arow][ach] = rA[1];
            *(uint4*)&sB[0][kr0][g0 * 32 + cl0] = rB[0][0];
            *(uint4*)&sB[1][kr0][g0 * 32 + cl0] = rB[1][0];
            *(uint4*)&sB[0][kr1][g1 * 32 + cl1] = rB[0][1];
            *(uint4*)&sB[1][kr1][g1 * 32 + cl1] = rB[1][1];
            __syncthreads();

            // prefetch next chunk into regs (overlaps with mma below)
            if (kc < 15) {
                const int k0 = (kc + 1) * 32;
                rA[0] = ldcg4(rhi + (size_t)(mb + arow) * Hh + k0 + ach);
                rA[1] = ldcg4(rlo + (size_t)(mb + arow) * Hh + k0 + ach);
                rB[0][0] = *(const uint4*)(Bhi + (size_t)(k0 + kr0) * Gg + g0 * Hh + ct * 32 + cl0);
                rB[1][0] = *(const uint4*)(Blo + (size_t)(k0 + kr0) * Gg + g0 * Hh + ct * 32 + cl0);
                rB[0][1] = *(const uint4*)(Bhi + (size_t)(k0 + kr1) * Gg + g1 * Hh + ct * 32 + cl1);
                rB[1][1] = *(const uint4*)(Blo + (size_t)(k0 + kr1) * Gg + g1 * Hh + ct * 32 + cl1);
            }

#pragma unroll
            for (int kk = 0; kk < 32; kk += 16) {
                uint32_t af[2][2][4];
#pragma unroll
                for (int p = 0; p < 2; p++)
#pragma unroll
                    for (int mi = 0; mi < 2; mi++) {
                        uint32_t addr = smem_u32(
                            &sA[p][wm * 32 + mi * 16 + (l & 7) + ((l >> 3) & 1) * 8][kk + (l >> 4) * 8]);
                        ldsm4(af[p][mi], addr);
                    }
                uint32_t bfr[2][4][2];
                const int lm = l & 15;
                const int krow = (lm & 7) + ((lm >> 3) & 1) * 8;
                const int gsel = l >> 4;
#pragma unroll
                for (int p = 0; p < 2; p++)
#pragma unroll
                    for (int gp = 0; gp < 2; gp++) {
                        uint32_t addr = smem_u32(&sB[p][kk + krow][(gp * 2 + gsel) * 32 + wn * 8]);
                        uint32_t r0, r1, r2, r3;
                        ldsm4t(r0, r1, r2, r3, addr);
                        bfr[p][gp * 2][0] = r0; bfr[p][gp * 2][1] = r1;
                        bfr[p][gp * 2 + 1][0] = r2; bfr[p][gp * 2 + 1][1] = r3;
                    }
#pragma unroll
                for (int mi = 0; mi < 2; mi++)
#pragma unroll
                    for (int g = 0; g < 4; g++) {
                        mma_bf16(acc[mi][g], af[0][mi], bfr[0][g]);
                        mma_bf16(acc[mi][g], af[0][mi], bfr[1][g]);
                        mma_bf16(acc[mi][g], af[1][mi], bfr[0][g]);
                    }
            }
            __syncthreads();
        }

        // ---- fused gate epilogue (c in registers) ----
#pragma unroll
        for (int mi = 0; mi < 2; mi++) {
#pragma unroll
            for (int rr = 0; rr < 2; rr++) {
                int b = mb + wm * 32 + mi * 16 + r + rr * 8;
                float cn[2], hn[2];
#pragma unroll
                for (int cc = 0; cc < 2; cc++) {
                    float pi = acc[mi][0][rr * 2 + cc] + (cc ? xv[mi][rr][0].y : xv[mi][rr][0].x);
                    float pf = acc[mi][1][rr * 2 + cc] + (cc ? xv[mi][rr][1].y : xv[mi][rr][1].x);
                    float pg = acc[mi][2][rr * 2 + cc] + (cc ? xv[mi][rr][2].y : xv[mi][rr][2].x);
                    float po = acc[mi][3][rr * 2 + cc] + (cc ? xv[mi][rr][3].y : xv[mi][rr][3].x);
                    float ig = fast_sigmoid(pi);
                    float fg = fast_sigmoid(pf);
                    float gg = fast_tanh(pg);
                    float og = fast_sigmoid(po);
                    float cv = fg * c_reg[mi][rr][cc] + ig * gg;
                    c_reg[mi][rr][cc] = cv;
                    cn[cc] = cv;
                    hn[cc] = og * fast_tanh(cv);
                }
                (void)cn;
                *(float2*)(hs + ((size_t)b * Tt + t) * Hh + col) = make_float2(hn[0], hn[1]);
                __nv_bfloat16 h0 = __float2bfloat16(hn[0]);
                __nv_bfloat16 h1 = __float2bfloat16(hn[1]);
                __nv_bfloat162 hh; hh.x = h0; hh.y = h1;
                *(__nv_bfloat162*)(whi + (size_t)b * Hh + col) = hh;
                __nv_bfloat162 ll;
                ll.x = __float2bfloat16(hn[0] - __bfloat162float(h0));
                ll.y = __float2bfloat16(hn[1] - __bfloat162float(h1));
                *(__nv_bfloat162*)(wlo + (size_t)b * Hh + col) = ll;
            }
        }

        // ---- grid-wide barrier (all 128 CTAs co-resident) ----
        if (t < Tt - 1) {
            __syncthreads();
            if (tid == 0) {
                __threadfence();
                atomicAdd(&g_bar, 1u);
                const unsigned target = (unsigned)NCTA * (unsigned)(t + 1);
                unsigned v;
                do {
                    asm volatile("ld.acquire.gpu.u32 %0,[%1];" : "=r"(v) : "l"(&g_bar));
                    if (v < target) __nanosleep(32);
                } while (v < target);
            }
            __syncthreads();
        }
    }
}

// ---------------- fused head: fc1 + BN1 + leaky + fc2 + BN2 + relu ---------
#define HEAD_DYN_SMEM ((512 * 32 + 512 * 33) * sizeof(float))

__global__ void __launch_bounds__(256) head_kernel(
    const float* __restrict__ fc1_w, const float* __restrict__ fc1_b,
    const float* __restrict__ fc2_w, const float* __restrict__ fc2_b,
    const float* __restrict__ bn1_g, const float* __restrict__ bn1_b,
    const float* __restrict__ bn2_g, const float* __restrict__ bn2_b,
    float* __restrict__ out)
{
    extern __shared__ float sm[];
    float* fc1t = sm;              // [512][32]
    float* sa   = sm + 512 * 32;   // [512][33]

    __shared__ float red1[8], red2[8];
    __shared__ float zbuf[Bsz];
    __shared__ float fc2s[32];
    __shared__ float stats[4];

    const int t = blockIdx.x;
    const int tid = threadIdx.x;
    const int warp = tid >> 5, lane = tid & 31;

    if (tid < 32) fc2s[tid] = fc2_w[tid];
    for (int idx = tid; idx < 32 * 512; idx += 256) {
        int o = idx >> 9, k = idx & 511;
        fc1t[k * 32 + o] = fc1_w[idx];
    }
    __syncthreads();

    const float bias_o = fc1_b[lane];
    for (int pr = 0; pr < 32; pr++) {
        const int b0 = warp * 64 + pr * 2;
        const int b1 = b0 + 1;
        const float4* r0 = (const float4*)(g_hs + ((size_t)b0 * Tt + t) * Hh);
        const float4* r1 = (const float4*)(g_hs + ((size_t)b1 * Tt + t) * Hh);
        float a0 = bias_o, a1 = bias_o;
#pragma unroll 4
        for (int k4 = 0; k4 < Hh / 4; k4++) {
            float4 v0 = r0[k4], v1 = r1[k4];
            const float* fp = fc1t + (k4 * 4) * 32 + lane;
            float wv;
            wv = fp[0];  a0 += v0.x * wv; a1 += v1.x * wv;
            wv = fp[32]; a0 += v0.y * wv; a1 += v1.y * wv;
            wv = fp[64]; a0 += v0.z * wv; a1 += v1.z * wv;
            wv = fp[96]; a0 += v0.w * wv; a1 += v1.w * wv;
        }
        sa[b0 * 33 + lane] = a0;
        sa[b1 * 33 + lane] = a1;
    }
    __syncthreads();

    float s = 0.f, ss = 0.f;
    for (int idx = tid; idx < Bsz * 32; idx += 256) {
        float v = sa[(idx >> 5) * 33 + (idx & 31)];
        s += v; ss += v * v;
    }
#pragma unroll
    for (int off = 16; off; off >>= 1) {
        s  += __shfl_down_sync(0xffffffffu, s,  off);
        ss += __shfl_down_sync(0xffffffffu, ss, off);
    }
    if (lane == 0) { red1[warp] = s; red2[warp] = ss; }
    __syncthreads();
    if (tid == 0) {
        float S = 0.f, SS = 0.f;
        for (int wv = 0; wv < 8; wv++) { S += red1[wv]; SS += red2[wv]; }
        float m = S / 16384.f;
        float v = SS / 16384.f - m * m;
        stats[0] = m;
        stats[1] = rsqrtf(v + 1e-5f);
    }
    __syncthreads();

    const float m1 = stats[0], inv1 = stats[1];
    const float g1 = bn1_g[t], be1 = bn1_b[t];
    const float f2b = fc2_b[0];

    for (int b = tid; b < Bsz; b += 256) {
        float acc = f2b;
#pragma unroll
        for (int o = 0; o < 32; o++) {
            float a = (sa[b * 33 + o] - m1) * inv1 * g1 + be1;
            a = a > 0.f ? a : 0.1f * a;
            acc += a * fc2s[o];
        }
        zbuf[b] = acc;
    }
    __syncthreads();

    float s2 = 0.f, ss2 = 0.f;
    for (int b = tid; b < Bsz; b += 256) { float v = zbuf[b]; s2 += v; ss2 += v * v; }
#pragma unroll
    for (int off = 16; off; off >>= 1) {
        s2  += __shfl_down_sync(0xffffffffu, s2,  off);
        ss2 += __shfl_down_sync(0xffffffffu, ss2, off);
    }
    if (lane == 0) { red1[warp] = s2; red2[warp] = ss2; }
    __syncthreads();
    if (tid == 0) {
        float S = 0.f, SS = 0.f;
        for (int wv = 0; wv < 8; wv++) { S += red1[wv]; SS += red2[wv]; }
        float m = S / (float)Bsz;
        float v = SS / (float)Bsz - m * m;
        stats[2] = m;
        stats[3] = rsqrtf(v + 1e-5f);
    }
    __syncthreads();

    const float m2 = stats[2], inv2 = stats[3];
    const float g2 = bn2_g[t], be2 = bn2_b[t];
    for (int b = tid; b < Bsz; b += 256) {
        float v = (zbuf[b] - m2) * inv2 * g2 + be2;
        out[(size_t)b * Tt + t] = v > 0.f ? v : 0.f;
    }
}

// ---------------- launch ----------------------------------------------------
extern "C" void kernel_launch(void* const* d_in, const int* in_sizes, int n_in,
                              void* d_out, int out_size)
{
    const float* x     = (const float*)d_in[0];
    const float* Wih   = (const float*)d_in[1];
    const float* Whh   = (const float*)d_in[2];
    const float* bih   = (const float*)d_in[3];
    const float* bhh   = (const float*)d_in[4];
    const float* fc1_w = (const float*)d_in[5];
    const float* fc1_b = (const float*)d_in[6];
    const float* fc2_w = (const float*)d_in[7];
    const float* fc2_b = (const float*)d_in[8];
    const float* bn1_g = (const float*)d_in[9];
    const float* bn1_b = (const float*)d_in[10];
    const float* bn2_g = (const float*)d_in[11];
    const float* bn2_b = (const float*)d_in[12];
    float* out = (float*)d_out;

    cudaFuncSetAttribute(head_kernel, cudaFuncAttributeMaxDynamicSharedMemorySize,
                         (int)HEAD_DYN_SMEM);

    float *d_xg, *d_hs;
    __nv_bfloat16 *d_xhi, *d_xlo, *d_wihhi, *d_wihlo, *d_whhhi, *d_whhlo;
    __nv_bfloat16 *d_hhi0, *d_hlo0, *d_hhi1, *d_hlo1;
    cudaGetSymbolAddress((void**)&d_xg,    g_xg);
    cudaGetSymbolAddress((void**)&d_hs,    g_hs);
    cudaGetSymbolAddress((void**)&d_xhi,   g_x_hi);
    cudaGetSymbolAddress((void**)&d_xlo,   g_x_lo);
    cudaGetSymbolAddress((void**)&d_wihhi, g_wih_hi);
    cudaGetSymbolAddress((void**)&d_wihlo, g_wih_lo);
    cudaGetSymbolAddress((void**)&d_whhhi, g_whh_hi);
    cudaGetSymbolAddress((void**)&d_whhlo, g_whh_lo);
    cudaGetSymbolAddress((void**)&d_hhi0,  g_h_hi0);
    cudaGetSymbolAddress((void**)&d_hlo0,  g_h_lo0);
    cudaGetSymbolAddress((void**)&d_hhi1,  g_h_hi1);
    cudaGetSymbolAddress((void**)&d_hlo1,  g_h_lo1);

    // prep
    conv_w_kernel<<<(Gg * Hh + 255) / 256, 256>>>(Whh, d_whhhi, d_whhlo, Gg, Hh);
    conv_w_kernel<<<(Gg * Ii + 255) / 256, 256>>>(Wih, d_wihhi, d_wihlo, Gg, Ii);
    conv_x_kernel<<<((int)((size_t)Bsz * Tt * Ii) + 255) / 256, 256>>>(
        x, d_xhi, d_xlo, Bsz * Tt * Ii);
    init_kernel<<<(Bsz * Hh + 255) / 256, 256>>>(d_hhi0, d_hlo0);

    // xg = x @ Wih^T + bih + bhh
    xg_gemm_kernel<<<dim3(Gg / 128, (Bsz * Tt) / 128), 256>>>(
        d_xhi, d_xlo, d_wihhi, d_wihlo, bih, bhh, d_xg);

    // persistent scan: one kernel, 256 timesteps, software grid barrier
    scan_persist_kernel<<<NCTA, 256>>>(d_whhhi, d_whhlo,
                                       d_hhi0, d_hlo0, d_hhi1, d_hlo1,
                                       d_xg, d_hs);

    // fused head
    head_kernel<<<Tt, 256, HEAD_DYN_SMEM>>>(fc1_w, fc1_b, fc2_w, fc2_b,
                                            bn1_g, bn1_b, bn2_g, bn2_b, out);
}

// round 6
// speedup vs baseline: 2.1876x; 1.0655x over previous
#include <cuda_runtime.h>
#include <cuda_bf16.h>
#include <math.h>
#include <stdint.h>

#define Bsz 512
#define Tt  256
#define Ii  256
#define Hh  512
#define Gg  2048   // 4H
#define NCTA 128   // persistent scan grid

// ---------------- scratch (device globals; no allocation allowed) ----------
__device__ __align__(256) float g_xg[(size_t)Bsz * Tt * Gg];   // 1.07 GB
__device__ __align__(256) float g_hs[(size_t)Bsz * Tt * Hh];   // 256 MB
__device__ __align__(256) __nv_bfloat16 g_x_hi[(size_t)Bsz * Tt * Ii];
__device__ __align__(256) __nv_bfloat16 g_x_lo[(size_t)Bsz * Tt * Ii];
__device__ __align__(256) __nv_bfloat16 g_wih_hi[Ii * Gg];   // transposed [256][2048]
__device__ __align__(256) __nv_bfloat16 g_wih_lo[Ii * Gg];
__device__ __align__(256) __nv_bfloat16 g_whh_hi[Gg * Hh];   // plain [2048][512]
__device__ __align__(256) __nv_bfloat16 g_whh_lo[Gg * Hh];
__device__ __align__(256) __nv_bfloat16 g_h_hi0[Bsz * Hh];
__device__ __align__(256) __nv_bfloat16 g_h_lo0[Bsz * Hh];
__device__ __align__(256) __nv_bfloat16 g_h_hi1[Bsz * Hh];
__device__ __align__(256) __nv_bfloat16 g_h_lo1[Bsz * Hh];
__device__ unsigned g_bar;

// ---------------- PTX helpers ----------------------------------------------
__device__ __forceinline__ uint32_t smem_u32(const void* p) {
    return (uint32_t)__cvta_generic_to_shared(p);
}
__device__ __forceinline__ void ldsm4(uint32_t* r, uint32_t addr) {
    asm volatile("ldmatrix.sync.aligned.m8n8.x4.shared.b16 {%0,%1,%2,%3},[%4];\n"
                 : "=r"(r[0]), "=r"(r[1]), "=r"(r[2]), "=r"(r[3]) : "r"(addr));
}
__device__ __forceinline__ void ldsm4t(uint32_t& r0, uint32_t& r1, uint32_t& r2, uint32_t& r3,
                                       uint32_t addr) {
    asm volatile("ldmatrix.sync.aligned.m8n8.x4.trans.shared.b16 {%0,%1,%2,%3},[%4];\n"
                 : "=r"(r0), "=r"(r1), "=r"(r2), "=r"(r3) : "r"(addr));
}
__device__ __forceinline__ void mma_bf16(float* c, const uint32_t* a, const uint32_t* b) {
    asm volatile("mma.sync.aligned.m16n8k16.row.col.f32.bf16.bf16.f32 "
                 "{%0,%1,%2,%3},{%4,%5,%6,%7},{%8,%9},{%0,%1,%2,%3};\n"
                 : "+f"(c[0]), "+f"(c[1]), "+f"(c[2]), "+f"(c[3])
                 : "r"(a[0]), "r"(a[1]), "r"(a[2]), "r"(a[3]), "r"(b[0]), "r"(b[1]));
}
__device__ __forceinline__ void cpasync16(uint32_t dst, const void* src) {
    asm volatile("cp.async.cg.shared.global [%0],[%1],16;\n" :: "r"(dst), "l"(src));
}
#define CP_COMMIT() asm volatile("cp.async.commit_group;\n" ::: "memory")
#define CP_WAIT(n)  asm volatile("cp.async.wait_group %0;\n" :: "n"(n) : "memory")

__device__ __forceinline__ float fast_sigmoid(float x) {
    return __fdividef(1.f, 1.f + __expf(-x));
}
__device__ __forceinline__ float fast_tanh(float x) {
    return 1.f - __fdividef(2.f, __expf(2.f * x) + 1.f);
}

// ---------------- prep kernels ---------------------------------------------
// [N][K] fp32 -> transposed [K][N=2048] bf16 hi/lo (for xg GEMM's Wih)
__global__ void conv_w_kernel(const float* __restrict__ src,
                              __nv_bfloat16* __restrict__ dhi,
                              __nv_bfloat16* __restrict__ dlo, int N, int K) {
    int idx = blockIdx.x * 256 + threadIdx.x;
    if (idx >= N * K) return;
    int n = idx / K, k = idx - n * K;
    float v = src[idx];
    __nv_bfloat16 h = __float2bfloat16(v);
    dhi[(size_t)k * Gg + n] = h;
    dlo[(size_t)k * Gg + n] = __float2bfloat16(v - __bfloat162float(h));
}

// plain elementwise split (layout preserved)
__global__ void conv_x_kernel(const float* __restrict__ src,
                              __nv_bfloat16* __restrict__ dhi,
                              __nv_bfloat16* __restrict__ dlo, int n) {
    int idx = blockIdx.x * 256 + threadIdx.x;
    if (idx >= n) return;
    float v = src[idx];
    __nv_bfloat16 h = __float2bfloat16(v);
    dhi[idx] = h;
    dlo[idx] = __float2bfloat16(v - __bfloat162float(h));
}

__global__ void init_kernel(__nv_bfloat16* __restrict__ hhi,
                            __nv_bfloat16* __restrict__ hlo) {
    int i = blockIdx.x * 256 + threadIdx.x;
    if (i == 0) g_bar = 0u;
    if (i < Bsz * Hh) {
        hhi[i] = __float2bfloat16(0.f);
        hlo[i] = __float2bfloat16(0.f);
    }
}

// ---------------- xg GEMM (HMMA bf16x3, unchanged from round 4) -------------
__global__ void __launch_bounds__(256) xg_gemm_kernel(
    const __nv_bfloat16* __restrict__ Ahi, const __nv_bfloat16* __restrict__ Alo,
    const __nv_bfloat16* __restrict__ Bhi, const __nv_bfloat16* __restrict__ Blo,
    const float* __restrict__ bih, const float* __restrict__ bhh,
    float* __restrict__ C)
{
    __shared__ __align__(16) __nv_bfloat16 sA[2][128][40];
    __shared__ __align__(16) __nv_bfloat16 sB[2][32][136];
    const int tid = threadIdx.x;
    const int l = tid & 31, w = tid >> 5;
    const int wm = w >> 1, wn = w & 1;
    const int n0 = blockIdx.x * 128;
    const int m0 = blockIdx.y * 128;

    float acc[2][8][4];
#pragma unroll
    for (int mi = 0; mi < 2; mi++)
#pragma unroll
        for (int nt = 0; nt < 8; nt++)
#pragma unroll
            for (int q = 0; q < 4; q++) acc[mi][nt][q] = 0.f;

    for (int k0 = 0; k0 < Ii; k0 += 32) {
        for (int s = tid; s < 512; s += 256) {
            int row = s >> 2, ch = (s & 3) * 8;
            *(uint4*)&sA[0][row][ch] = *(const uint4*)(Ahi + (size_t)(m0 + row) * Ii + k0 + ch);
            *(uint4*)&sA[1][row][ch] = *(const uint4*)(Alo + (size_t)(m0 + row) * Ii + k0 + ch);
        }
        for (int s = tid; s < 512; s += 256) {
            int kr = s >> 4, ch = (s & 15) * 8;
            *(uint4*)&sB[0][kr][ch] = *(const uint4*)(Bhi + (size_t)(k0 + kr) * Gg + n0 + ch);
            *(uint4*)&sB[1][kr][ch] = *(const uint4*)(Blo + (size_t)(k0 + kr) * Gg + n0 + ch);
        }
        __syncthreads();
#pragma unroll
        for (int kk = 0; kk < 32; kk += 16) {
            uint32_t af[2][2][4];
#pragma unroll
            for (int p = 0; p < 2; p++)
#pragma unroll
                for (int mi = 0; mi < 2; mi++) {
                    uint32_t addr = smem_u32(
                        &sA[p][wm * 32 + mi * 16 + (l & 15)][kk + (l >> 4) * 8]);
                    ldsm4(af[p][mi], addr);
                }
            uint32_t bfr[2][8][2];
            const int krow = (l & 15);
            const int csel = (l >> 4) * 8;
#pragma unroll
            for (int p = 0; p < 2; p++)
#pragma unroll
                for (int jp = 0; jp < 4; jp++) {
                    uint32_t addr = smem_u32(&sB[p][kk + krow][wn * 64 + jp * 16 + csel]);
                    uint32_t r0, r1, r2, r3;
                    ldsm4t(r0, r1, r2, r3, addr);
                    bfr[p][jp * 2][0] = r0; bfr[p][jp * 2][1] = r1;
                    bfr[p][jp * 2 + 1][0] = r2; bfr[p][jp * 2 + 1][1] = r3;
                }
#pragma unroll
            for (int mi = 0; mi < 2; mi++)
#pragma unroll
                for (int nt = 0; nt < 8; nt++) {
                    mma_bf16(acc[mi][nt], af[0][mi], bfr[0][nt]);
                    mma_bf16(acc[mi][nt], af[0][mi], bfr[1][nt]);
                    mma_bf16(acc[mi][nt], af[1][mi], bfr[0][nt]);
                }
        }
        __syncthreads();
    }

    const int r = l >> 2, cq = (l & 3) * 2;
#pragma unroll
    for (int mi = 0; mi < 2; mi++)
#pragma unroll
        for (int nt = 0; nt < 8; nt++) {
            const int col = n0 + wn * 64 + nt * 8 + cq;
            float bs0 = bih[col] + bhh[col];
            float bs1 = bih[col + 1] + bhh[col + 1];
#pragma unroll
            for (int rr = 0; rr < 2; rr++) {
                int m = m0 + wm * 32 + mi * 16 + r + rr * 8;
                float2 v = make_float2(acc[mi][nt][rr * 2 + 0] + bs0,
                                       acc[mi][nt][rr * 2 + 1] + bs1);
                *(float2*)(C + (size_t)m * Gg + col) = v;
            }
        }
}

// ---------------- persistent HMMA scan --------------------------------------
// 128 CTAs = 4 batch tiles (128) x 32 ncol tiles (64 = 4 gates x 16 hcols).
// Whh slice (hi+lo) RESIDENT in smem all 256 steps. c in registers.
// h staged via cp.async.cg 3-stage pipeline (16 K-chunks of 32).
// Warps: 8 x m16, each warp covers all 64 ncols -> gate epilogue in-thread.
//
// smem layout (dynamic):
//  sB: [half][512 k][72] bf16      off 0,      147456 B
//  sA: [buf3][half][128 m][40] bf16 off 147456, 61440 B
#define SCAN_SB_OFF   0
#define SCAN_SB_HALF  73728          // 512*72*2
#define SCAN_SA_OFF   147456
#define SCAN_SA_SLOT  10240          // 128*40*2
#define SCAN_SMEM     208896

__global__ void __launch_bounds__(256, 1) scan_hmma_kernel(
    const __nv_bfloat16* __restrict__ whh_hi, const __nv_bfloat16* __restrict__ whh_lo,
    __nv_bfloat16* __restrict__ h_hi0, __nv_bfloat16* __restrict__ h_lo0,
    __nv_bfloat16* __restrict__ h_hi1, __nv_bfloat16* __restrict__ h_lo1,
    const float* __restrict__ xg, float* __restrict__ hs)
{
    extern __shared__ __align__(128) char sm[];
    const uint32_t smb = smem_u32(sm);
    const int tid = threadIdx.x, l = tid & 31, w = tid >> 5;
    const int bt = blockIdx.x >> 5;       // batch tile 0..3
    const int ctile = blockIdx.x & 31;    // ncol tile 0..31
    const int mb = bt * 128;
    const int hc0 = ctile * 16;

    // ---- fill resident B: sB[half][k][n_local], n_local = gate*16 + hcol ----
#pragma unroll
    for (int half = 0; half < 2; half++) {
        const __nv_bfloat16* src = half ? whh_lo : whh_hi;
        __nv_bfloat16* dstb = (__nv_bfloat16*)(sm + SCAN_SB_OFF + half * SCAN_SB_HALF);
        for (int s = tid; s < 4096; s += 256) {
            int n = s >> 6;               // 0..63
            int kg = (s & 63) * 8;        // 0..504
            int gate = n >> 4, hc = n & 15;
            const __nv_bfloat16* sp = src + (size_t)(gate * Hh + hc0 + hc) * Hh + kg;
            __nv_bfloat16 v[8];
            *(uint4*)v = *(const uint4*)sp;
#pragma unroll
            for (int e = 0; e < 8; e++) dstb[(kg + e) * 72 + n] = v[e];
        }
    }
    __syncthreads();

    // per-thread staging indices: 1024 16B transfers per chunk, 4 per thread
    // s = tid + i*256 : half = s>>9, row = (s&511)>>2, kg = (s&3)*8
    // per-thread ldsm bases
    const uint32_t aoff = (uint32_t)(((w * 16 + (l & 15)) * 40 + (l >> 4) * 8) * 2);
    const uint32_t boff = (uint32_t)(((l & 15) * 72 + (l >> 4) * 8) * 2);

    float c_reg[8];
#pragma unroll
    for (int q = 0; q < 8; q++) c_reg[q] = 0.f;

    const int a_ep = (l & 3) * 2;           // hcol base for epilogue
    const int r0_ep = mb + w * 16 + (l >> 2);

    for (int t = 0; t < Tt; t++) {
        const __nv_bfloat16* rhi = (t & 1) ? h_hi1 : h_hi0;
        const __nv_bfloat16* rlo = (t & 1) ? h_lo1 : h_lo0;
        __nv_bfloat16* whi = (t & 1) ? h_hi0 : h_hi1;
        __nv_bfloat16* wlo = (t & 1) ? h_lo0 : h_lo1;

        float acc[8][4];
#pragma unroll
        for (int nf = 0; nf < 8; nf++)
#pragma unroll
            for (int q = 0; q < 4; q++) acc[nf][q] = 0.f;

        // issue chunks 0 and 1
#pragma unroll
        for (int pc = 0; pc < 2; pc++) {
#pragma unroll
            for (int i = 0; i < 4; i++) {
                int s = tid + i * 256;
                int half = s >> 9, rem = s & 511;
                int row = rem >> 2, kg = (rem & 3) * 8;
                const __nv_bfloat16* src = (half ? rlo : rhi)
                    + (size_t)(mb + row) * Hh + pc * 32 + kg;
                uint32_t dst = smb + SCAN_SA_OFF + (uint32_t)(((pc % 3) * 2 + half) * SCAN_SA_SLOT)
                             + (uint32_t)((row * 40 + kg) * 2);
                cpasync16(dst, src);
            }
            CP_COMMIT();
        }

        for (int c = 0; c < 16; c++) {
            if (c + 2 < 16) {
                const int pc = c + 2;
#pragma unroll
                for (int i = 0; i < 4; i++) {
                    int s = tid + i * 256;
                    int half = s >> 9, rem = s & 511;
                    int row = rem >> 2, kg = (rem & 3) * 8;
                    const __nv_bfloat16* src = (half ? rlo : rhi)
                        + (size_t)(mb + row) * Hh + pc * 32 + kg;
                    uint32_t dst = smb + SCAN_SA_OFF
                                 + (uint32_t)(((pc % 3) * 2 + half) * SCAN_SA_SLOT)
                                 + (uint32_t)((row * 40 + kg) * 2);
                    cpasync16(dst, src);
                }
                CP_COMMIT();
                CP_WAIT(2);
            } else if (c == 14) {
                CP_WAIT(1);
            } else {
                CP_WAIT(0);
            }
            __syncthreads();

            const uint32_t aHi = smb + SCAN_SA_OFF + (uint32_t)(((c % 3) * 2 + 0) * SCAN_SA_SLOT) + aoff;
            const uint32_t aLo = aHi + SCAN_SA_SLOT;
#pragma unroll
            for (int kk = 0; kk < 32; kk += 16) {
                uint32_t ah[4], al[4];
                ldsm4(ah, aHi + kk * 2);
                ldsm4(al, aLo + kk * 2);
                uint32_t bh[8][2], bl[8][2];
                const uint32_t bRow = (uint32_t)((c * 32 + kk) * 144);
#pragma unroll
                for (int jp = 0; jp < 4; jp++) {
                    uint32_t r0, r1, r2, r3;
                    ldsm4t(r0, r1, r2, r3, smb + SCAN_SB_OFF + boff + bRow + jp * 32);
                    bh[jp * 2][0] = r0; bh[jp * 2][1] = r1;
                    bh[jp * 2 + 1][0] = r2; bh[jp * 2 + 1][1] = r3;
                }
#pragma unroll
                for (int jp = 0; jp < 4; jp++) {
                    uint32_t r0, r1, r2, r3;
                    ldsm4t(r0, r1, r2, r3,
                           smb + SCAN_SB_OFF + SCAN_SB_HALF + boff + bRow + jp * 32);
                    bl[jp * 2][0] = r0; bl[jp * 2][1] = r1;
                    bl[jp * 2 + 1][0] = r2; bl[jp * 2 + 1][1] = r3;
                }
#pragma unroll
                for (int nf = 0; nf < 8; nf++) {
                    mma_bf16(acc[nf], ah, bh[nf]);
                    mma_bf16(acc[nf], ah, bl[nf]);
                    mma_bf16(acc[nf], al, bh[nf]);
                }
            }
        }

        // ---- gate epilogue: c in regs, all 8 warps ----
#pragma unroll
        for (int rr = 0; rr < 2; rr++) {
            const int b = r0_ep + rr * 8;
            const float* xb = xg + ((size_t)b * Tt + t) * Gg + hc0;
            float pre[4][4];
#pragma unroll
            for (int g = 0; g < 4; g++) {
                float2 f2a = *(const float2*)(xb + g * Hh + a_ep);
                float2 f2b = *(const float2*)(xb + g * Hh + a_ep + 8);
                pre[g][0] = acc[g * 2][rr * 2]         + f2a.x;
                pre[g][1] = acc[g * 2][rr * 2 + 1]     + f2a.y;
                pre[g][2] = acc[g * 2 + 1][rr * 2]     + f2b.x;
                pre[g][3] = acc[g * 2 + 1][rr * 2 + 1] + f2b.y;
            }
            float hn[4];
#pragma unroll
            for (int s = 0; s < 4; s++) {
                float ig = fast_sigmoid(pre[0][s]);
                float fg = fast_sigmoid(pre[1][s]);
                float gg = fast_tanh(pre[2][s]);
                float og = fast_sigmoid(pre[3][s]);
                float cv = fg * c_reg[rr * 4 + s] + ig * gg;
                c_reg[rr * 4 + s] = cv;
                hn[s] = og * fast_tanh(cv);
            }
            float* hrow = hs + ((size_t)b * Tt + t) * Hh + hc0;
            *(float2*)(hrow + a_ep)     = make_float2(hn[0], hn[1]);
            *(float2*)(hrow + a_ep + 8) = make_float2(hn[2], hn[3]);
            __nv_bfloat16 hh[4], ll[4];
#pragma unroll
            for (int s = 0; s < 4; s++) {
                hh[s] = __float2bfloat16(hn[s]);
                ll[s] = __float2bfloat16(hn[s] - __bfloat162float(hh[s]));
            }
            __nv_bfloat162 p01, p23;
            p01.x = hh[0]; p01.y = hh[1]; p23.x = hh[2]; p23.y = hh[3];
            *(__nv_bfloat162*)(whi + (size_t)b * Hh + hc0 + a_ep)     = p01;
            *(__nv_bfloat162*)(whi + (size_t)b * Hh + hc0 + a_ep + 8) = p23;
            p01.x = ll[0]; p01.y = ll[1]; p23.x = ll[2]; p23.y = ll[3];
            *(__nv_bfloat162*)(wlo + (size_t)b * Hh + hc0 + a_ep)     = p01;
            *(__nv_bfloat162*)(wlo + (size_t)b * Hh + hc0 + a_ep + 8) = p23;
        }

        // ---- grid barrier ----
        if (t < Tt - 1) {
            __syncthreads();
            if (tid == 0) {
                __threadfence();
                atomicAdd(&g_bar, 1u);
                const unsigned target = (unsigned)NCTA * (unsigned)(t + 1);
                unsigned v;
                do {
                    asm volatile("ld.acquire.gpu.u32 %0,[%1];" : "=r"(v) : "l"(&g_bar));
                    if (v < target) __nanosleep(32);
                } while (v < target);
            }
            __syncthreads();
        }
    }
}

// ---------------- fused head: fc1 + BN1 + leaky + fc2 + BN2 + relu ---------
#define HEAD_DYN_SMEM ((512 * 32 + 512 * 33) * sizeof(float))

__global__ void __launch_bounds__(256) head_kernel(
    const float* __restrict__ fc1_w, const float* __restrict__ fc1_b,
    const float* __restrict__ fc2_w, const float* __restrict__ fc2_b,
    const float* __restrict__ bn1_g, const float* __restrict__ bn1_b,
    const float* __restrict__ bn2_g, const float* __restrict__ bn2_b,
    float* __restrict__ out)
{
    extern __shared__ float smf[];
    float* fc1t = smf;             // [512][32]
    float* sa   = smf + 512 * 32;  // [512][33]

    __shared__ float red1[8], red2[8];
    __shared__ float zbuf[Bsz];
    __shared__ float fc2s[32];
    __shared__ float stats[4];

    const int t = blockIdx.x;
    const int tid = threadIdx.x;
    const int warp = tid >> 5, lane = tid & 31;

    if (tid < 32) fc2s[tid] = fc2_w[tid];
    for (int idx = tid; idx < 32 * 512; idx += 256) {
        int o = idx >> 9, k = idx & 511;
        fc1t[k * 32 + o] = fc1_w[idx];
    }
    __syncthreads();

    const float bias_o = fc1_b[lane];
    for (int pr = 0; pr < 32; pr++) {
        const int b0 = warp * 64 + pr * 2;
        const int b1 = b0 + 1;
        const float4* r0 = (const float4*)(g_hs + ((size_t)b0 * Tt + t) * Hh);
        const float4* r1 = (const float4*)(g_hs + ((size_t)b1 * Tt + t) * Hh);
        float a0 = bias_o, a1 = bias_o;
#pragma unroll 4
        for (int k4 = 0; k4 < Hh / 4; k4++) {
            float4 v0 = r0[k4], v1 = r1[k4];
            const float* fp = fc1t + (k4 * 4) * 32 + lane;
            float wv;
            wv = fp[0];  a0 += v0.x * wv; a1 += v1.x * wv;
            wv = fp[32]; a0 += v0.y * wv; a1 += v1.y * wv;
            wv = fp[64]; a0 += v0.z * wv; a1 += v1.z * wv;
            wv = fp[96]; a0 += v0.w * wv; a1 += v1.w * wv;
        }
        sa[b0 * 33 + lane] = a0;
        sa[b1 * 33 + lane] = a1;
    }
    __syncthreads();

    float s = 0.f, ss = 0.f;
    for (int idx = tid; idx < Bsz * 32; idx += 256) {
        float v = sa[(idx >> 5) * 33 + (idx & 31)];
        s += v; ss += v * v;
    }
#pragma unroll
    for (int off = 16; off; off >>= 1) {
        s  += __shfl_down_sync(0xffffffffu, s,  off);
        ss += __shfl_down_sync(0xffffffffu, ss, off);
    }
    if (lane == 0) { red1[warp] = s; red2[warp] = ss; }
    __syncthreads();
    if (tid == 0) {
        float S = 0.f, SS = 0.f;
        for (int wv = 0; wv < 8; wv++) { S += red1[wv]; SS += red2[wv]; }
        float m = S / 16384.f;
        float v = SS / 16384.f - m * m;
        stats[0] = m;
        stats[1] = rsqrtf(v + 1e-5f);
    }
    __syncthreads();

    const float m1 = stats[0], inv1 = stats[1];
    const float g1 = bn1_g[t], be1 = bn1_b[t];
    const float f2b = fc2_b[0];

    for (int b = tid; b < Bsz; b += 256) {
        float acc = f2b;
#pragma unroll
        for (int o = 0; o < 32; o++) {
            float a = (sa[b * 33 + o] - m1) * inv1 * g1 + be1;
            a = a > 0.f ? a : 0.1f * a;
            acc += a * fc2s[o];
        }
        zbuf[b] = acc;
    }
    __syncthreads();

    float s2 = 0.f, ss2 = 0.f;
    for (int b = tid; b < Bsz; b += 256) { float v = zbuf[b]; s2 += v; ss2 += v * v; }
#pragma unroll
    for (int off = 16; off; off >>= 1) {
        s2  += __shfl_down_sync(0xffffffffu, s2,  off);
        ss2 += __shfl_down_sync(0xffffffffu, ss2, off);
    }
    if (lane == 0) { red1[warp] = s2; red2[warp] = ss2; }
    __syncthreads();
    if (tid == 0) {
        float S = 0.f, SS = 0.f;
        for (int wv = 0; wv < 8; wv++) { S += red1[wv]; SS += red2[wv]; }
        float m = S / (float)Bsz;
        float v = SS / (float)Bsz - m * m;
        stats[2] = m;
        stats[3] = rsqrtf(v + 1e-5f);
    }
    __syncthreads();

    const float m2 = stats[2], inv2 = stats[3];
    const float g2 = bn2_g[t], be2 = bn2_b[t];
    for (int b = tid; b < Bsz; b += 256) {
        float v = (zbuf[b] - m2) * inv2 * g2 + be2;
        out[(size_t)b * Tt + t] = v > 0.f ? v : 0.f;
    }
}

// ---------------- launch ----------------------------------------------------
extern "C" void kernel_launch(void* const* d_in, const int* in_sizes, int n_in,
                              void* d_out, int out_size)
{
    const float* x     = (const float*)d_in[0];
    const float* Wih   = (const float*)d_in[1];
    const float* Whh   = (const float*)d_in[2];
    const float* bih   = (const float*)d_in[3];
    const float* bhh   = (const float*)d_in[4];
    const float* fc1_w = (const float*)d_in[5];
    const float* fc1_b = (const float*)d_in[6];
    const float* fc2_w = (const float*)d_in[7];
    const float* fc2_b = (const float*)d_in[8];
    const float* bn1_g = (const float*)d_in[9];
    const float* bn1_b = (const float*)d_in[10];
    const float* bn2_g = (const float*)d_in[11];
    const float* bn2_b = (const float*)d_in[12];
    float* out = (float*)d_out;

    cudaFuncSetAttribute(head_kernel, cudaFuncAttributeMaxDynamicSharedMemorySize,
                         (int)HEAD_DYN_SMEM);
    cudaFuncSetAttribute(scan_hmma_kernel, cudaFuncAttributeMaxDynamicSharedMemorySize,
                         SCAN_SMEM);

    float *d_xg, *d_hs;
    __nv_bfloat16 *d_xhi, *d_xlo, *d_wihhi, *d_wihlo, *d_whhhi, *d_whhlo;
    __nv_bfloat16 *d_hhi0, *d_hlo0, *d_hhi1, *d_hlo1;
    cudaGetSymbolAddress((void**)&d_xg,    g_xg);
    cudaGetSymbolAddress((void**)&d_hs,    g_hs);
    cudaGetSymbolAddress((void**)&d_xhi,   g_x_hi);
    cudaGetSymbolAddress((void**)&d_xlo,   g_x_lo);
    cudaGetSymbolAddress((void**)&d_wihhi, g_wih_hi);
    cudaGetSymbolAddress((void**)&d_wihlo, g_wih_lo);
    cudaGetSymbolAddress((void**)&d_whhhi, g_whh_hi);
    cudaGetSymbolAddress((void**)&d_whhlo, g_whh_lo);
    cudaGetSymbolAddress((void**)&d_hhi0,  g_h_hi0);
    cudaGetSymbolAddress((void**)&d_hlo0,  g_h_lo0);
    cudaGetSymbolAddress((void**)&d_hhi1,  g_h_hi1);
    cudaGetSymbolAddress((void**)&d_hlo1,  g_h_lo1);

    // prep
    conv_w_kernel<<<(Gg * Ii + 255) / 256, 256>>>(Wih, d_wihhi, d_wihlo, Gg, Ii);
    conv_x_kernel<<<(Gg * Hh + 255) / 256, 256>>>(Whh, d_whhhi, d_whhlo, Gg * Hh);
    conv_x_kernel<<<((int)((size_t)Bsz * Tt * Ii) + 255) / 256, 256>>>(
        x, d_xhi, d_xlo, Bsz * Tt * Ii);
    init_kernel<<<(Bsz * Hh + 255) / 256, 256>>>(d_hhi0, d_hlo0);

    // xg = x @ Wih^T + bih + bhh
    xg_gemm_kernel<<<dim3(Gg / 128, (Bsz * Tt) / 128), 256>>>(
        d_xhi, d_xlo, d_wihhi, d_wihlo, bih, bhh, d_xg);

    // persistent HMMA scan
    scan_hmma_kernel<<<NCTA, 256, SCAN_SMEM>>>(d_whhhi, d_whhlo,
                                               d_hhi0, d_hlo0, d_hhi1, d_hlo1,
                                               d_xg, d_hs);

    // fused head
    head_kernel<<<Tt, 256, HEAD_DYN_SMEM>>>(fc1_w, fc1_b, fc2_w, fc2_b,
                                            bn1_g, bn1_b, bn2_g, bn2_b, out);
}